// round 1
// baseline (speedup 1.0000x reference)
#include <cuda_runtime.h>
#include <math.h>

// Problem constants
#define BB 2
#define NN 16384
#define CC 8
#define DD 256
#define HH 64
#define WW 64

// Scratch (device globals: allocation-free)
__device__ float g_qn[(size_t)BB * NN * DD];            //  33.5 MB
__device__ float g_q[(size_t)BB * NN * DD];             //  33.5 MB
__device__ float g_sampled[(size_t)BB * NN * CC * DD];  // 268 MB   (B,N,C,D)
__device__ float g_kv[(size_t)BB * NN * CC * 2 * DD];   // 536 MB   (B,N,C,2D)
__device__ float g_attn[(size_t)BB * NN * DD];          //  33.5 MB

// ---------------------------------------------------------------------------
// LayerNorm: one block per row, 256 threads (one element each)
// ---------------------------------------------------------------------------
__global__ void ln_kernel(const float* __restrict__ x,
                          const float* __restrict__ gamma,
                          const float* __restrict__ beta,
                          float* __restrict__ out) {
    int row = blockIdx.x;
    int d = threadIdx.x;
    float v = x[(size_t)row * DD + d];

    __shared__ float red[8];
    __shared__ float s_mu, s_rstd;

    // sum -> mean
    float s = v;
    #pragma unroll
    for (int o = 16; o > 0; o >>= 1) s += __shfl_xor_sync(0xFFFFFFFFu, s, o);
    if ((d & 31) == 0) red[d >> 5] = s;
    __syncthreads();
    if (d == 0) {
        float t = 0.f;
        #pragma unroll
        for (int i = 0; i < 8; i++) t += red[i];
        s_mu = t / (float)DD;
    }
    __syncthreads();
    float mu = s_mu;

    // variance
    float c = v - mu;
    float s2 = c * c;
    #pragma unroll
    for (int o = 16; o > 0; o >>= 1) s2 += __shfl_xor_sync(0xFFFFFFFFu, s2, o);
    __syncthreads();   // protect red[] reuse
    if ((d & 31) == 0) red[d >> 5] = s2;
    __syncthreads();
    if (d == 0) {
        float t = 0.f;
        #pragma unroll
        for (int i = 0; i < 8; i++) t += red[i];
        s_rstd = rsqrtf(t / (float)DD + 1e-5f);
    }
    __syncthreads();

    out[(size_t)row * DD + d] = c * s_rstd * gamma[d] + beta[d];
}

// ---------------------------------------------------------------------------
// Bilinear sample: one block per (b,n,c), thread = d. Output layout (B,N,C,D).
// ---------------------------------------------------------------------------
__global__ void sample_kernel(const float* __restrict__ feat,
                              const float* __restrict__ coords,
                              float* __restrict__ out) {
    int bid = blockIdx.x;                // (b*NN + n)*CC + c
    int c = bid % CC;
    int n = (bid / CC) % NN;
    int b = bid / (CC * NN);
    int d = threadIdx.x;

    const float* pc = coords + (((size_t)(b * CC + c) * NN + n) * 2);
    float xf = (pc[0] + 1.f) * 0.5f * (float)(WW - 1);
    float yf = (pc[1] + 1.f) * 0.5f * (float)(HH - 1);
    float x0f = floorf(xf), y0f = floorf(yf);
    float wx1 = xf - x0f, wy1 = yf - y0f;
    int x0 = (int)x0f, y0 = (int)y0f;

    const float* fb = feat + ((size_t)(b * CC + c) * HH * WW) * DD;

    float acc = 0.f;
    #pragma unroll
    for (int dy = 0; dy < 2; dy++) {
        #pragma unroll
        for (int dx = 0; dx < 2; dx++) {
            int xi = x0 + dx, yi = y0 + dy;
            float w = (dy ? wy1 : 1.f - wy1) * (dx ? wx1 : 1.f - wx1);
            bool inb = (xi >= 0) && (xi < WW) && (yi >= 0) && (yi < HH);
            int xc = min(max(xi, 0), WW - 1);
            int yc = min(max(yi, 0), HH - 1);
            float v = fb[((size_t)yc * WW + xc) * DD + d];
            acc += v * (inb ? w : 0.f);
        }
    }
    out[(((size_t)(b * NN + n) * CC) + c) * DD + d] = acc;
}

// ---------------------------------------------------------------------------
// Tiled SGEMM: C[M,Nc] = A[M,K] @ W[K,Nc] + bias (+ resid). 128x128x16 tiles,
// 256 threads, 8x8 microtile per thread. M % 128 == 0, Nc % 128 == 0, K % 16 == 0.
// ---------------------------------------------------------------------------
__global__ void __launch_bounds__(256, 1)
gemm_bias_kernel(const float* __restrict__ A, const float* __restrict__ W,
                 const float* __restrict__ bias, const float* __restrict__ resid,
                 float* __restrict__ Cm, int M, int K, int Nc) {
    const int BM = 128, BN = 128, BK = 16;
    __shared__ float As[BK][BM];
    __shared__ float Ws[BK][BN];

    int tid = threadIdx.x;
    int tx = tid & 15;        // column group
    int ty = tid >> 4;        // row group
    int row0 = blockIdx.y * BM;
    int col0 = blockIdx.x * BN;

    float acc[8][8];
    #pragma unroll
    for (int i = 0; i < 8; i++)
        #pragma unroll
        for (int j = 0; j < 8; j++) acc[i][j] = 0.f;

    for (int k0 = 0; k0 < K; k0 += BK) {
        // A tile: 128x16 = 512 float4, transposed into As[k][m]
        #pragma unroll
        for (int i = tid; i < 512; i += 256) {
            int m = i >> 2;
            int kq = i & 3;
            float4 v = *(const float4*)(A + (size_t)(row0 + m) * K + k0 + kq * 4);
            As[kq * 4 + 0][m] = v.x;
            As[kq * 4 + 1][m] = v.y;
            As[kq * 4 + 2][m] = v.z;
            As[kq * 4 + 3][m] = v.w;
        }
        // W tile: 16x128 = 512 float4, direct
        #pragma unroll
        for (int i = tid; i < 512; i += 256) {
            int kk = i >> 5;
            int nq = i & 31;
            *(float4*)&Ws[kk][nq * 4] =
                *(const float4*)(W + (size_t)(k0 + kk) * Nc + col0 + nq * 4);
        }
        __syncthreads();

        #pragma unroll
        for (int kk = 0; kk < BK; kk++) {
            float af[8], wf[8];
            *(float4*)&af[0] = *(const float4*)&As[kk][ty * 8];
            *(float4*)&af[4] = *(const float4*)&As[kk][ty * 8 + 4];
            *(float4*)&wf[0] = *(const float4*)&Ws[kk][tx * 8];
            *(float4*)&wf[4] = *(const float4*)&Ws[kk][tx * 8 + 4];
            #pragma unroll
            for (int i = 0; i < 8; i++)
                #pragma unroll
                for (int j = 0; j < 8; j++)
                    acc[i][j] = fmaf(af[i], wf[j], acc[i][j]);
        }
        __syncthreads();
    }

    #pragma unroll
    for (int i = 0; i < 8; i++) {
        int r = row0 + ty * 8 + i;
        #pragma unroll
        for (int j = 0; j < 8; j += 4) {
            int cix = col0 + tx * 8 + j;
            float4 v;
            v.x = acc[i][j + 0] + bias[cix + 0];
            v.y = acc[i][j + 1] + bias[cix + 1];
            v.z = acc[i][j + 2] + bias[cix + 2];
            v.w = acc[i][j + 3] + bias[cix + 3];
            if (resid) {
                float4 rv = *(const float4*)(resid + (size_t)r * Nc + cix);
                v.x += rv.x; v.y += rv.y; v.z += rv.z; v.w += rv.w;
            }
            *(float4*)(Cm + (size_t)r * Nc + cix) = v;
        }
    }
}

// ---------------------------------------------------------------------------
// Attention: one block per (b,n), 256 threads. Warp c computes score_c;
// softmax over C=8; out[d] = sum_c attn_c * v[c,d].
// ---------------------------------------------------------------------------
__global__ void attn_kernel(const int* __restrict__ vmask,
                            const float* __restrict__ q,
                            const float* __restrict__ kv,
                            float* __restrict__ out) {
    int bn = blockIdx.x;
    int b = bn / NN;
    int n = bn % NN;
    int tid = threadIdx.x;
    int w = tid >> 5, lane = tid & 31;

    __shared__ float qs[DD];
    __shared__ float sc[CC];

    qs[tid] = q[(size_t)bn * DD + tid];
    __syncthreads();

    const float* kvb = kv + (size_t)bn * CC * 2 * DD;

    // warp w -> channel w
    float s = 0.f;
    #pragma unroll
    for (int i = lane; i < DD; i += 32)
        s += qs[i] * kvb[(size_t)w * 2 * DD + i];
    #pragma unroll
    for (int o = 16; o > 0; o >>= 1) s += __shfl_xor_sync(0xFFFFFFFFu, s, o);
    if (lane == 0) {
        int vm = vmask[((size_t)b * CC + w) * NN + n];
        sc[w] = vm ? s * 0.0625f : -INFINITY;   // / sqrt(256)
    }
    __syncthreads();

    // softmax over 8 (computed redundantly by every thread)
    float m = -INFINITY;
    #pragma unroll
    for (int c = 0; c < CC; c++) m = fmaxf(m, sc[c]);
    float a[CC];
    if (m == -INFINITY) {
        #pragma unroll
        for (int c = 0; c < CC; c++) a[c] = 0.f;
    } else {
        float denom = 0.f;
        #pragma unroll
        for (int c = 0; c < CC; c++) { a[c] = __expf(sc[c] - m); denom += a[c]; }
        float inv = 1.f / denom;
        #pragma unroll
        for (int c = 0; c < CC; c++) a[c] *= inv;
    }

    float o = 0.f;
    #pragma unroll
    for (int c = 0; c < CC; c++)
        o += a[c] * kvb[(size_t)c * 2 * DD + DD + tid];
    out[(size_t)bn * DD + tid] = o;
}

// ---------------------------------------------------------------------------
// Launch
// ---------------------------------------------------------------------------
extern "C" void kernel_launch(void* const* d_in, const int* in_sizes, int n_in,
                              void* d_out, int out_size) {
    const float* queries = (const float*)d_in[0];
    const float* feat    = (const float*)d_in[1];
    const float* coords  = (const float*)d_in[2];
    const int*   vmask   = (const int*)d_in[3];
    const float* Wq      = (const float*)d_in[4];
    const float* bq      = (const float*)d_in[5];
    const float* Wkv     = (const float*)d_in[6];
    const float* bkv     = (const float*)d_in[7];
    const float* Wo      = (const float*)d_in[8];
    const float* bo      = (const float*)d_in[9];
    const float* gamma   = (const float*)d_in[10];
    const float* beta    = (const float*)d_in[11];
    float* out = (float*)d_out;

    float *p_qn, *p_q, *p_sampled, *p_kv, *p_attn;
    cudaGetSymbolAddress((void**)&p_qn, g_qn);
    cudaGetSymbolAddress((void**)&p_q, g_q);
    cudaGetSymbolAddress((void**)&p_sampled, g_sampled);
    cudaGetSymbolAddress((void**)&p_kv, g_kv);
    cudaGetSymbolAddress((void**)&p_attn, g_attn);

    const int Mq = BB * NN;          // 32768
    const int Mkv = BB * NN * CC;    // 262144

    ln_kernel<<<Mq, 256>>>(queries, gamma, beta, p_qn);
    sample_kernel<<<Mkv, 256>>>(feat, coords, p_sampled);
    gemm_bias_kernel<<<dim3(DD / 128, Mq / 128), 256>>>(
        p_qn, Wq, bq, nullptr, p_q, Mq, DD, DD);
    gemm_bias_kernel<<<dim3(2 * DD / 128, Mkv / 128), 256>>>(
        p_sampled, Wkv, bkv, nullptr, p_kv, Mkv, DD, 2 * DD);
    attn_kernel<<<Mq, 256>>>(vmask, p_q, p_kv, p_attn);
    gemm_bias_kernel<<<dim3(DD / 128, Mq / 128), 256>>>(
        p_attn, Wo, bo, queries, out, Mq, DD, DD);
}

// round 2
// speedup vs baseline: 1.9684x; 1.9684x over previous
#include <cuda_runtime.h>
#include <math.h>

// Problem constants
#define BB 2
#define NN 16384
#define CC 8
#define DD 256
#define HH 64
#define WW 64

// Scratch (device globals: allocation-free)
__device__ float g_qn[(size_t)BB * NN * DD];            //  33.5 MB
__device__ float g_q[(size_t)BB * NN * DD];             //  33.5 MB
__device__ float g_sampled[(size_t)BB * NN * CC * DD];  // 268 MB   (B,N,C,D)
__device__ float g_kv[(size_t)BB * NN * CC * 2 * DD];   // 536 MB   (B,N,C,2D)
__device__ float g_attn[(size_t)BB * NN * DD];          //  33.5 MB

__device__ __forceinline__ unsigned f2tf32(float f) {
    unsigned u;
    asm("cvt.rna.tf32.f32 %0, %1;" : "=r"(u) : "f"(f));
    return u;
}

// ---------------------------------------------------------------------------
// LayerNorm: one block per row, 256 threads (one element each)
// ---------------------------------------------------------------------------
__global__ void ln_kernel(const float* __restrict__ x,
                          const float* __restrict__ gamma,
                          const float* __restrict__ beta,
                          float* __restrict__ out) {
    int row = blockIdx.x;
    int d = threadIdx.x;
    float v = x[(size_t)row * DD + d];

    __shared__ float red[8];
    __shared__ float s_mu, s_rstd;

    float s = v;
    #pragma unroll
    for (int o = 16; o > 0; o >>= 1) s += __shfl_xor_sync(0xFFFFFFFFu, s, o);
    if ((d & 31) == 0) red[d >> 5] = s;
    __syncthreads();
    if (d == 0) {
        float t = 0.f;
        #pragma unroll
        for (int i = 0; i < 8; i++) t += red[i];
        s_mu = t / (float)DD;
    }
    __syncthreads();
    float mu = s_mu;

    float c = v - mu;
    float s2 = c * c;
    #pragma unroll
    for (int o = 16; o > 0; o >>= 1) s2 += __shfl_xor_sync(0xFFFFFFFFu, s2, o);
    __syncthreads();
    if ((d & 31) == 0) red[d >> 5] = s2;
    __syncthreads();
    if (d == 0) {
        float t = 0.f;
        #pragma unroll
        for (int i = 0; i < 8; i++) t += red[i];
        s_rstd = rsqrtf(t / (float)DD + 1e-5f);
    }
    __syncthreads();

    out[(size_t)row * DD + d] = c * s_rstd * gamma[d] + beta[d];
}

// ---------------------------------------------------------------------------
// Bilinear sample: one block per (b,n,c), thread = d. Output layout (B,N,C,D).
// ---------------------------------------------------------------------------
__global__ void sample_kernel(const float* __restrict__ feat,
                              const float* __restrict__ coords,
                              float* __restrict__ out) {
    int bid = blockIdx.x;                // (b*NN + n)*CC + c
    int c = bid % CC;
    int n = (bid / CC) % NN;
    int b = bid / (CC * NN);
    int d = threadIdx.x;

    const float* pc = coords + (((size_t)(b * CC + c) * NN + n) * 2);
    float xf = (pc[0] + 1.f) * 0.5f * (float)(WW - 1);
    float yf = (pc[1] + 1.f) * 0.5f * (float)(HH - 1);
    float x0f = floorf(xf), y0f = floorf(yf);
    float wx1 = xf - x0f, wy1 = yf - y0f;
    int x0 = (int)x0f, y0 = (int)y0f;

    const float* fb = feat + ((size_t)(b * CC + c) * HH * WW) * DD;

    float acc = 0.f;
    #pragma unroll
    for (int dy = 0; dy < 2; dy++) {
        #pragma unroll
        for (int dx = 0; dx < 2; dx++) {
            int xi = x0 + dx, yi = y0 + dy;
            float w = (dy ? wy1 : 1.f - wy1) * (dx ? wx1 : 1.f - wx1);
            bool inb = (xi >= 0) && (xi < WW) && (yi >= 0) && (yi < HH);
            int xc = min(max(xi, 0), WW - 1);
            int yc = min(max(yi, 0), HH - 1);
            float v = fb[((size_t)yc * WW + xc) * DD + d];
            acc += v * (inb ? w : 0.f);
        }
    }
    out[(((size_t)(b * NN + n) * CC) + c) * DD + d] = acc;
}

// ---------------------------------------------------------------------------
// TF32 tensor-core GEMM: C[M,Nc] = A[M,K] @ W[K,Nc] + bias (+ resid).
// BM=128, BN=128, BK=16, 256 threads (8 warps, 64x32 warp tiles),
// mma.sync.m16n8k8.tf32, double-buffered smem, stride-136 padding
// (conflict-free fragment loads: bank = 8*tg + g).
// Requires M%128==0, Nc%128==0, K%16==0.
// ---------------------------------------------------------------------------
__global__ void __launch_bounds__(256, 1)
gemm_tf32_kernel(const float* __restrict__ A, const float* __restrict__ W,
                 const float* __restrict__ bias, const float* __restrict__ resid,
                 float* __restrict__ Cm, int M, int K, int Nc) {
    const int BK = 16;
    const int LDS = 136;   // padded row stride (floats)
    __shared__ unsigned As[2][BK][LDS];
    __shared__ unsigned Bs[2][BK][LDS];

    int tid = threadIdx.x;
    int lane = tid & 31;
    int wid = tid >> 5;
    int wm = wid >> 2;          // 0..1  (M dimension)
    int wn = wid & 3;           // 0..3  (N dimension)
    int g = lane >> 2;          // groupID 0..7
    int tg = lane & 3;          // thread-in-group 0..3

    size_t row0 = (size_t)blockIdx.y * 128;
    size_t col0 = (size_t)blockIdx.x * 128;

    // ldg index decomposition
    int a_m = tid >> 2;         // 0..63 (and +64)
    int a_kq = tid & 3;         // float4 index within row
    int b_kk = tid >> 5;        // 0..7 (and +8)
    int b_nq = tid & 31;        // float4 col index

    const float* Aptr = A + (row0 + a_m) * (size_t)K + a_kq * 4;
    const float* Bptr = W + (size_t)b_kk * Nc + col0 + b_nq * 4;

    float acc[4][4][4];
    #pragma unroll
    for (int i = 0; i < 4; i++)
        #pragma unroll
        for (int j = 0; j < 4; j++)
            #pragma unroll
            for (int r = 0; r < 4; r++) acc[i][j][r] = 0.f;

    // ---- prologue: load k-tile 0 into buffer 0
    {
        float4 av0 = *(const float4*)(Aptr);
        float4 av1 = *(const float4*)(Aptr + 64 * (size_t)K);
        float4 bv0 = *(const float4*)(Bptr);
        float4 bv1 = *(const float4*)(Bptr + 8 * (size_t)Nc);
        As[0][a_kq * 4 + 0][a_m] = f2tf32(av0.x);
        As[0][a_kq * 4 + 1][a_m] = f2tf32(av0.y);
        As[0][a_kq * 4 + 2][a_m] = f2tf32(av0.z);
        As[0][a_kq * 4 + 3][a_m] = f2tf32(av0.w);
        As[0][a_kq * 4 + 0][a_m + 64] = f2tf32(av1.x);
        As[0][a_kq * 4 + 1][a_m + 64] = f2tf32(av1.y);
        As[0][a_kq * 4 + 2][a_m + 64] = f2tf32(av1.z);
        As[0][a_kq * 4 + 3][a_m + 64] = f2tf32(av1.w);
        Bs[0][b_kk][b_nq * 4 + 0] = f2tf32(bv0.x);
        Bs[0][b_kk][b_nq * 4 + 1] = f2tf32(bv0.y);
        Bs[0][b_kk][b_nq * 4 + 2] = f2tf32(bv0.z);
        Bs[0][b_kk][b_nq * 4 + 3] = f2tf32(bv0.w);
        Bs[0][b_kk + 8][b_nq * 4 + 0] = f2tf32(bv1.x);
        Bs[0][b_kk + 8][b_nq * 4 + 1] = f2tf32(bv1.y);
        Bs[0][b_kk + 8][b_nq * 4 + 2] = f2tf32(bv1.z);
        Bs[0][b_kk + 8][b_nq * 4 + 3] = f2tf32(bv1.w);
    }
    __syncthreads();

    int cur = 0;
    for (int k0 = 0; k0 < K; k0 += BK) {
        int next = k0 + BK;
        float4 av0, av1, bv0, bv1;
        if (next < K) {
            av0 = *(const float4*)(Aptr + next);
            av1 = *(const float4*)(Aptr + next + 64 * (size_t)K);
            bv0 = *(const float4*)(Bptr + (size_t)next * Nc);
            bv1 = *(const float4*)(Bptr + (size_t)(next + 8) * Nc);
        }

        // ---- compute on buffer `cur`
        #pragma unroll
        for (int ks = 0; ks < 2; ks++) {
            int kb = ks * 8;
            unsigned a[4][4], b[4][2];
            #pragma unroll
            for (int mt = 0; mt < 4; mt++) {
                int m = wm * 64 + mt * 16 + g;
                a[mt][0] = As[cur][kb + tg][m];
                a[mt][1] = As[cur][kb + tg][m + 8];
                a[mt][2] = As[cur][kb + tg + 4][m];
                a[mt][3] = As[cur][kb + tg + 4][m + 8];
            }
            #pragma unroll
            for (int nt = 0; nt < 4; nt++) {
                int n = wn * 32 + nt * 8 + g;
                b[nt][0] = Bs[cur][kb + tg][n];
                b[nt][1] = Bs[cur][kb + tg + 4][n];
            }
            #pragma unroll
            for (int mt = 0; mt < 4; mt++)
                #pragma unroll
                for (int nt = 0; nt < 4; nt++) {
                    asm volatile(
                        "mma.sync.aligned.m16n8k8.row.col.f32.tf32.tf32.f32 "
                        "{%0,%1,%2,%3}, {%4,%5,%6,%7}, {%8,%9}, {%0,%1,%2,%3};\n"
                        : "+f"(acc[mt][nt][0]), "+f"(acc[mt][nt][1]),
                          "+f"(acc[mt][nt][2]), "+f"(acc[mt][nt][3])
                        : "r"(a[mt][0]), "r"(a[mt][1]), "r"(a[mt][2]), "r"(a[mt][3]),
                          "r"(b[nt][0]), "r"(b[nt][1]));
                }
        }

        if (next < K) {
            int nx = cur ^ 1;
            As[nx][a_kq * 4 + 0][a_m] = f2tf32(av0.x);
            As[nx][a_kq * 4 + 1][a_m] = f2tf32(av0.y);
            As[nx][a_kq * 4 + 2][a_m] = f2tf32(av0.z);
            As[nx][a_kq * 4 + 3][a_m] = f2tf32(av0.w);
            As[nx][a_kq * 4 + 0][a_m + 64] = f2tf32(av1.x);
            As[nx][a_kq * 4 + 1][a_m + 64] = f2tf32(av1.y);
            As[nx][a_kq * 4 + 2][a_m + 64] = f2tf32(av1.z);
            As[nx][a_kq * 4 + 3][a_m + 64] = f2tf32(av1.w);
            Bs[nx][b_kk][b_nq * 4 + 0] = f2tf32(bv0.x);
            Bs[nx][b_kk][b_nq * 4 + 1] = f2tf32(bv0.y);
            Bs[nx][b_kk][b_nq * 4 + 2] = f2tf32(bv0.z);
            Bs[nx][b_kk][b_nq * 4 + 3] = f2tf32(bv0.w);
            Bs[nx][b_kk + 8][b_nq * 4 + 0] = f2tf32(bv1.x);
            Bs[nx][b_kk + 8][b_nq * 4 + 1] = f2tf32(bv1.y);
            Bs[nx][b_kk + 8][b_nq * 4 + 2] = f2tf32(bv1.z);
            Bs[nx][b_kk + 8][b_nq * 4 + 3] = f2tf32(bv1.w);
            __syncthreads();
        }
        cur ^= 1;
    }

    // ---- epilogue: bias (+resid) and store
    #pragma unroll
    for (int mt = 0; mt < 4; mt++) {
        size_t r = row0 + wm * 64 + mt * 16 + g;
        #pragma unroll
        for (int nt = 0; nt < 4; nt++) {
            size_t c = col0 + wn * 32 + nt * 8 + tg * 2;
            float2 bb = *(const float2*)(bias + c);
            float2 v0, v1;
            v0.x = acc[mt][nt][0] + bb.x;
            v0.y = acc[mt][nt][1] + bb.y;
            v1.x = acc[mt][nt][2] + bb.x;
            v1.y = acc[mt][nt][3] + bb.y;
            if (resid) {
                float2 r0 = *(const float2*)(resid + r * Nc + c);
                float2 r1 = *(const float2*)(resid + (r + 8) * Nc + c);
                v0.x += r0.x; v0.y += r0.y;
                v1.x += r1.x; v1.y += r1.y;
            }
            *(float2*)(Cm + r * Nc + c) = v0;
            *(float2*)(Cm + (r + 8) * Nc + c) = v1;
        }
    }
}

// ---------------------------------------------------------------------------
// Attention: one block per (b,n), 256 threads. Warp c computes score_c;
// softmax over C=8; out[d] = sum_c attn_c * v[c,d].
// ---------------------------------------------------------------------------
__global__ void attn_kernel(const int* __restrict__ vmask,
                            const float* __restrict__ q,
                            const float* __restrict__ kv,
                            float* __restrict__ out) {
    int bn = blockIdx.x;
    int b = bn / NN;
    int n = bn % NN;
    int tid = threadIdx.x;
    int w = tid >> 5, lane = tid & 31;

    __shared__ float qs[DD];
    __shared__ float sc[CC];

    qs[tid] = q[(size_t)bn * DD + tid];
    __syncthreads();

    const float* kvb = kv + (size_t)bn * CC * 2 * DD;

    float s = 0.f;
    #pragma unroll
    for (int i = lane; i < DD; i += 32)
        s += qs[i] * kvb[(size_t)w * 2 * DD + i];
    #pragma unroll
    for (int o = 16; o > 0; o >>= 1) s += __shfl_xor_sync(0xFFFFFFFFu, s, o);
    if (lane == 0) {
        int vm = vmask[((size_t)b * CC + w) * NN + n];
        sc[w] = vm ? s * 0.0625f : -INFINITY;
    }
    __syncthreads();

    float m = -INFINITY;
    #pragma unroll
    for (int c = 0; c < CC; c++) m = fmaxf(m, sc[c]);
    float a[CC];
    if (m == -INFINITY) {
        #pragma unroll
        for (int c = 0; c < CC; c++) a[c] = 0.f;
    } else {
        float denom = 0.f;
        #pragma unroll
        for (int c = 0; c < CC; c++) { a[c] = __expf(sc[c] - m); denom += a[c]; }
        float inv = 1.f / denom;
        #pragma unroll
        for (int c = 0; c < CC; c++) a[c] *= inv;
    }

    float o = 0.f;
    #pragma unroll
    for (int c = 0; c < CC; c++)
        o += a[c] * kvb[(size_t)c * 2 * DD + DD + tid];
    out[(size_t)bn * DD + tid] = o;
}

// ---------------------------------------------------------------------------
// Launch
// ---------------------------------------------------------------------------
extern "C" void kernel_launch(void* const* d_in, const int* in_sizes, int n_in,
                              void* d_out, int out_size) {
    const float* queries = (const float*)d_in[0];
    const float* feat    = (const float*)d_in[1];
    const float* coords  = (const float*)d_in[2];
    const int*   vmask   = (const int*)d_in[3];
    const float* Wq      = (const float*)d_in[4];
    const float* bq      = (const float*)d_in[5];
    const float* Wkv     = (const float*)d_in[6];
    const float* bkv     = (const float*)d_in[7];
    const float* Wo      = (const float*)d_in[8];
    const float* bo      = (const float*)d_in[9];
    const float* gamma   = (const float*)d_in[10];
    const float* beta    = (const float*)d_in[11];
    float* out = (float*)d_out;

    float *p_qn, *p_q, *p_sampled, *p_kv, *p_attn;
    cudaGetSymbolAddress((void**)&p_qn, g_qn);
    cudaGetSymbolAddress((void**)&p_q, g_q);
    cudaGetSymbolAddress((void**)&p_sampled, g_sampled);
    cudaGetSymbolAddress((void**)&p_kv, g_kv);
    cudaGetSymbolAddress((void**)&p_attn, g_attn);

    const int Mq = BB * NN;          // 32768
    const int Mkv = BB * NN * CC;    // 262144

    ln_kernel<<<Mq, 256>>>(queries, gamma, beta, p_qn);
    sample_kernel<<<Mkv, 256>>>(feat, coords, p_sampled);
    gemm_tf32_kernel<<<dim3(DD / 128, Mq / 128), 256>>>(
        p_qn, Wq, bq, nullptr, p_q, Mq, DD, DD);
    gemm_tf32_kernel<<<dim3(2 * DD / 128, Mkv / 128), 256>>>(
        p_sampled, Wkv, bkv, nullptr, p_kv, Mkv, DD, 2 * DD);
    attn_kernel<<<Mq, 256>>>(vmask, p_q, p_kv, p_attn);
    gemm_tf32_kernel<<<dim3(DD / 128, Mq / 128), 256>>>(
        p_attn, Wo, bo, queries, out, Mq, DD, DD);
}

// round 3
// speedup vs baseline: 6.7049x; 3.4063x over previous
#include <cuda_runtime.h>
#include <math.h>

// Problem constants
#define BB 2
#define NN 16384
#define CC 8
#define DD 256
#define HH 64
#define WW 64

// Scratch (device globals: allocation-free)
__device__ float g_qn[(size_t)BB * NN * DD];     // 33.5 MB
__device__ float g_t[(size_t)BB * NN * DD];      // 33.5 MB  (t = q @ Wk^T)
__device__ float g_u[(size_t)BB * NN * DD];      // 33.5 MB  (u = sum_c attn*sampled)
__device__ float g_s[(size_t)BB * NN];           // sum of attn per row
__device__ float g_Wqk[DD * DD];                 // Wq @ Wk^T
__device__ float g_Wvo[DD * DD];                 // Wv @ Wo
__device__ float g_bqk[DD];                      // bq @ Wk^T
__device__ float g_bvo[DD];                      // bv @ Wo
__device__ float g_wqbk[DD];                     // Wq @ bk
__device__ float g_bqbk[1];                      // bq . bk

__device__ __forceinline__ unsigned f2tf32(float f) {
    unsigned u;
    asm("cvt.rna.tf32.f32 %0, %1;" : "=r"(u) : "f"(f));
    return u;
}

// ---------------------------------------------------------------------------
// LayerNorm: one block per row, 256 threads
// ---------------------------------------------------------------------------
__global__ void ln_kernel(const float* __restrict__ x,
                          const float* __restrict__ gamma,
                          const float* __restrict__ beta,
                          float* __restrict__ out) {
    int row = blockIdx.x;
    int d = threadIdx.x;
    float v = x[(size_t)row * DD + d];

    __shared__ float red[8];
    __shared__ float s_mu, s_rstd;

    float s = v;
    #pragma unroll
    for (int o = 16; o > 0; o >>= 1) s += __shfl_xor_sync(0xFFFFFFFFu, s, o);
    if ((d & 31) == 0) red[d >> 5] = s;
    __syncthreads();
    if (d == 0) {
        float t = 0.f;
        #pragma unroll
        for (int i = 0; i < 8; i++) t += red[i];
        s_mu = t / (float)DD;
    }
    __syncthreads();
    float mu = s_mu;

    float c = v - mu;
    float s2 = c * c;
    #pragma unroll
    for (int o = 16; o > 0; o >>= 1) s2 += __shfl_xor_sync(0xFFFFFFFFu, s2, o);
    __syncthreads();
    if ((d & 31) == 0) red[d >> 5] = s2;
    __syncthreads();
    if (d == 0) {
        float t = 0.f;
        #pragma unroll
        for (int i = 0; i < 8; i++) t += red[i];
        s_rstd = rsqrtf(t / (float)DD + 1e-5f);
    }
    __syncthreads();

    out[(size_t)row * DD + d] = c * s_rstd * gamma[d] + beta[d];
}

// ---------------------------------------------------------------------------
// Weight folding (fp32, exact): Wqk = Wq@Wk^T, Wvo = Wv@Wo, bqk = bq@Wk^T,
// bvo = bv@Wo, wqbk = Wq@bk, bqbk = bq.bk.  Wk = Wkv[:, :256], Wv = Wkv[:, 256:],
// bk = bkv[:256], bv = bkv[256:].
// grid = 514 blocks x 256 threads.
// ---------------------------------------------------------------------------
__global__ void fold_kernel(const float* __restrict__ Wq,
                            const float* __restrict__ bq,
                            const float* __restrict__ Wkv,
                            const float* __restrict__ bkv,
                            const float* __restrict__ Wo) {
    __shared__ float srow[DD];
    int bidx = blockIdx.x;
    int tid = threadIdx.x;

    if (bidx < 256) {
        // Wqk[a][i] = sum_j Wq[a][j] * Wkv[i][j]   (a = bidx, i = tid)
        srow[tid] = Wq[(size_t)bidx * DD + tid];
        __syncthreads();
        float acc = 0.f;
        const float* wr = Wkv + (size_t)tid * (2 * DD);
        #pragma unroll 4
        for (int j = 0; j < DD; j++) acc += srow[j] * wr[j];
        g_Wqk[(size_t)bidx * DD + tid] = acc;
    } else if (bidx < 512) {
        // Wvo[i][j] = sum_k Wkv[i][256+k] * Wo[k][j]   (i = bidx-256, j = tid)
        int i = bidx - 256;
        srow[tid] = Wkv[(size_t)i * (2 * DD) + DD + tid];
        __syncthreads();
        float acc = 0.f;
        #pragma unroll 4
        for (int k = 0; k < DD; k++) acc += srow[k] * Wo[(size_t)k * DD + tid];
        g_Wvo[(size_t)i * DD + tid] = acc;
    } else if (bidx == 512) {
        float a1 = 0.f, a2 = 0.f;
        #pragma unroll 4
        for (int i = 0; i < DD; i++) a1 += bq[i] * Wkv[(size_t)i * (2 * DD) + tid];
        #pragma unroll 4
        for (int k = 0; k < DD; k++) a2 += bkv[DD + k] * Wo[(size_t)k * DD + tid];
        g_bqk[tid] = a1;
        g_bvo[tid] = a2;
    } else {
        float acc = 0.f;
        #pragma unroll 4
        for (int d = 0; d < DD; d++) acc += Wq[(size_t)tid * DD + d] * bkv[d];
        g_wqbk[tid] = acc;
        if (tid == 0) {
            float s = 0.f;
            for (int d = 0; d < DD; d++) s += bq[d] * bkv[d];
            g_bqbk[0] = s;
        }
    }
}

// ---------------------------------------------------------------------------
// TF32 tensor-core GEMM: C = A[M,K] @ W[K,Nc] + bias (+ resid) (+ svec[r]*bvec2[c]).
// BM=128, BN=128, BK=16, 256 threads, double-buffered smem, stride-136 pad.
// ---------------------------------------------------------------------------
__global__ void __launch_bounds__(256, 1)
gemm_tf32_kernel(const float* __restrict__ A, const float* __restrict__ W,
                 const float* __restrict__ bias, const float* __restrict__ resid,
                 const float* __restrict__ svec, const float* __restrict__ bvec2,
                 float* __restrict__ Cm, int M, int K, int Nc) {
    const int BK = 16;
    const int LDS = 136;
    __shared__ unsigned As[2][BK][LDS];
    __shared__ unsigned Bs[2][BK][LDS];

    int tid = threadIdx.x;
    int lane = tid & 31;
    int wid = tid >> 5;
    int wm = wid >> 2;
    int wn = wid & 3;
    int g = lane >> 2;
    int tg = lane & 3;

    size_t row0 = (size_t)blockIdx.y * 128;
    size_t col0 = (size_t)blockIdx.x * 128;

    int a_m = tid >> 2;
    int a_kq = tid & 3;
    int b_kk = tid >> 5;
    int b_nq = tid & 31;

    const float* Aptr = A + (row0 + a_m) * (size_t)K + a_kq * 4;
    const float* Bptr = W + (size_t)b_kk * Nc + col0 + b_nq * 4;

    float acc[4][4][4];
    #pragma unroll
    for (int i = 0; i < 4; i++)
        #pragma unroll
        for (int j = 0; j < 4; j++)
            #pragma unroll
            for (int r = 0; r < 4; r++) acc[i][j][r] = 0.f;

    {
        float4 av0 = *(const float4*)(Aptr);
        float4 av1 = *(const float4*)(Aptr + 64 * (size_t)K);
        float4 bv0 = *(const float4*)(Bptr);
        float4 bv1 = *(const float4*)(Bptr + 8 * (size_t)Nc);
        As[0][a_kq * 4 + 0][a_m] = f2tf32(av0.x);
        As[0][a_kq * 4 + 1][a_m] = f2tf32(av0.y);
        As[0][a_kq * 4 + 2][a_m] = f2tf32(av0.z);
        As[0][a_kq * 4 + 3][a_m] = f2tf32(av0.w);
        As[0][a_kq * 4 + 0][a_m + 64] = f2tf32(av1.x);
        As[0][a_kq * 4 + 1][a_m + 64] = f2tf32(av1.y);
        As[0][a_kq * 4 + 2][a_m + 64] = f2tf32(av1.z);
        As[0][a_kq * 4 + 3][a_m + 64] = f2tf32(av1.w);
        Bs[0][b_kk][b_nq * 4 + 0] = f2tf32(bv0.x);
        Bs[0][b_kk][b_nq * 4 + 1] = f2tf32(bv0.y);
        Bs[0][b_kk][b_nq * 4 + 2] = f2tf32(bv0.z);
        Bs[0][b_kk][b_nq * 4 + 3] = f2tf32(bv0.w);
        Bs[0][b_kk + 8][b_nq * 4 + 0] = f2tf32(bv1.x);
        Bs[0][b_kk + 8][b_nq * 4 + 1] = f2tf32(bv1.y);
        Bs[0][b_kk + 8][b_nq * 4 + 2] = f2tf32(bv1.z);
        Bs[0][b_kk + 8][b_nq * 4 + 3] = f2tf32(bv1.w);
    }
    __syncthreads();

    int cur = 0;
    for (int k0 = 0; k0 < K; k0 += BK) {
        int next = k0 + BK;
        float4 av0, av1, bv0, bv1;
        if (next < K) {
            av0 = *(const float4*)(Aptr + next);
            av1 = *(const float4*)(Aptr + next + 64 * (size_t)K);
            bv0 = *(const float4*)(Bptr + (size_t)next * Nc);
            bv1 = *(const float4*)(Bptr + (size_t)(next + 8) * Nc);
        }

        #pragma unroll
        for (int ks = 0; ks < 2; ks++) {
            int kb = ks * 8;
            unsigned a[4][4], b[4][2];
            #pragma unroll
            for (int mt = 0; mt < 4; mt++) {
                int m = wm * 64 + mt * 16 + g;
                a[mt][0] = As[cur][kb + tg][m];
                a[mt][1] = As[cur][kb + tg][m + 8];
                a[mt][2] = As[cur][kb + tg + 4][m];
                a[mt][3] = As[cur][kb + tg + 4][m + 8];
            }
            #pragma unroll
            for (int nt = 0; nt < 4; nt++) {
                int n = wn * 32 + nt * 8 + g;
                b[nt][0] = Bs[cur][kb + tg][n];
                b[nt][1] = Bs[cur][kb + tg + 4][n];
            }
            #pragma unroll
            for (int mt = 0; mt < 4; mt++)
                #pragma unroll
                for (int nt = 0; nt < 4; nt++) {
                    asm volatile(
                        "mma.sync.aligned.m16n8k8.row.col.f32.tf32.tf32.f32 "
                        "{%0,%1,%2,%3}, {%4,%5,%6,%7}, {%8,%9}, {%0,%1,%2,%3};\n"
                        : "+f"(acc[mt][nt][0]), "+f"(acc[mt][nt][1]),
                          "+f"(acc[mt][nt][2]), "+f"(acc[mt][nt][3])
                        : "r"(a[mt][0]), "r"(a[mt][1]), "r"(a[mt][2]), "r"(a[mt][3]),
                          "r"(b[nt][0]), "r"(b[nt][1]));
                }
        }

        if (next < K) {
            int nx = cur ^ 1;
            As[nx][a_kq * 4 + 0][a_m] = f2tf32(av0.x);
            As[nx][a_kq * 4 + 1][a_m] = f2tf32(av0.y);
            As[nx][a_kq * 4 + 2][a_m] = f2tf32(av0.z);
            As[nx][a_kq * 4 + 3][a_m] = f2tf32(av0.w);
            As[nx][a_kq * 4 + 0][a_m + 64] = f2tf32(av1.x);
            As[nx][a_kq * 4 + 1][a_m + 64] = f2tf32(av1.y);
            As[nx][a_kq * 4 + 2][a_m + 64] = f2tf32(av1.z);
            As[nx][a_kq * 4 + 3][a_m + 64] = f2tf32(av1.w);
            Bs[nx][b_kk][b_nq * 4 + 0] = f2tf32(bv0.x);
            Bs[nx][b_kk][b_nq * 4 + 1] = f2tf32(bv0.y);
            Bs[nx][b_kk][b_nq * 4 + 2] = f2tf32(bv0.z);
            Bs[nx][b_kk][b_nq * 4 + 3] = f2tf32(bv0.w);
            Bs[nx][b_kk + 8][b_nq * 4 + 0] = f2tf32(bv1.x);
            Bs[nx][b_kk + 8][b_nq * 4 + 1] = f2tf32(bv1.y);
            Bs[nx][b_kk + 8][b_nq * 4 + 2] = f2tf32(bv1.z);
            Bs[nx][b_kk + 8][b_nq * 4 + 3] = f2tf32(bv1.w);
            __syncthreads();
        }
        cur ^= 1;
    }

    #pragma unroll
    for (int mt = 0; mt < 4; mt++) {
        size_t r = row0 + wm * 64 + mt * 16 + g;
        #pragma unroll
        for (int nt = 0; nt < 4; nt++) {
            size_t c = col0 + wn * 32 + nt * 8 + tg * 2;
            float2 bb = *(const float2*)(bias + c);
            float2 v0, v1;
            v0.x = acc[mt][nt][0] + bb.x;
            v0.y = acc[mt][nt][1] + bb.y;
            v1.x = acc[mt][nt][2] + bb.x;
            v1.y = acc[mt][nt][3] + bb.y;
            if (resid) {
                float2 r0 = *(const float2*)(resid + r * Nc + c);
                float2 r1 = *(const float2*)(resid + (r + 8) * Nc + c);
                v0.x += r0.x; v0.y += r0.y;
                v1.x += r1.x; v1.y += r1.y;
            }
            if (svec) {
                float2 bv2 = *(const float2*)(bvec2 + c);
                float sv0 = svec[r], sv1 = svec[r + 8];
                v0.x += sv0 * bv2.x; v0.y += sv0 * bv2.y;
                v1.x += sv1 * bv2.x; v1.y += sv1 * bv2.y;
            }
            *(float2*)(Cm + r * Nc + c) = v0;
            *(float2*)(Cm + (r + 8) * Nc + c) = v1;
        }
    }
}

// ---------------------------------------------------------------------------
// Fused bilinear-sample + score + softmax + weighted-sum kernel.
// One block per (b,n), 256 threads; warp c handles channel c.
//   score[c] = (sampled[n,c] . t[n] + qn[n].wqbk + bqbk) / 16   (if valid)
//   u[n] = sum_c softmax(score)[c] * sampled[n,c]
//   s[n] = sum_c softmax(score)[c]   (0 if all masked)
// ---------------------------------------------------------------------------
__global__ void fused_attn_kernel(const float* __restrict__ feat,
                                  const float* __restrict__ coords,
                                  const int* __restrict__ vmask,
                                  const float* __restrict__ qn,
                                  const float* __restrict__ t,
                                  const float* __restrict__ wqbk,
                                  const float* __restrict__ bqbk,
                                  float* __restrict__ u,
                                  float* __restrict__ s_out) {
    int bn = blockIdx.x;
    int b = bn / NN;
    int n = bn % NN;
    int tid = threadIdx.x;
    int w = tid >> 5, lane = tid & 31;

    __shared__ float samp[CC][DD];
    __shared__ float sc[CC];
    __shared__ float red[8];
    __shared__ float s_sb;

    // s_bias = qn[bn] . wqbk + bqbk   (block reduction)
    float p = qn[(size_t)bn * DD + tid] * wqbk[tid];
    #pragma unroll
    for (int o = 16; o > 0; o >>= 1) p += __shfl_xor_sync(0xFFFFFFFFu, p, o);
    if (lane == 0) red[w] = p;
    __syncthreads();
    if (tid == 0) {
        float tt = 0.f;
        #pragma unroll
        for (int i = 0; i < 8; i++) tt += red[i];
        s_sb = tt + bqbk[0];
    }
    __syncthreads();

    // bilinear sample for channel w + dot with t[n]
    const float* pc = coords + ((size_t)(b * CC + w) * NN + n) * 2;
    float xf = (pc[0] + 1.f) * 0.5f * (float)(WW - 1);
    float yf = (pc[1] + 1.f) * 0.5f * (float)(HH - 1);
    float x0f = floorf(xf), y0f = floorf(yf);
    float wx = xf - x0f, wy = yf - y0f;
    int x0 = (int)x0f, y0 = (int)y0f;
    float w00 = (1.f - wy) * (1.f - wx);
    float w01 = (1.f - wy) * wx;
    float w10 = wy * (1.f - wx);
    float w11 = wy * wx;
    bool bx0 = (x0 >= 0) && (x0 < WW);
    bool bx1 = (x0 + 1 >= 0) && (x0 + 1 < WW);
    bool by0 = (y0 >= 0) && (y0 < HH);
    bool by1 = (y0 + 1 >= 0) && (y0 + 1 < HH);
    if (!(bx0 && by0)) w00 = 0.f;
    if (!(bx1 && by0)) w01 = 0.f;
    if (!(bx0 && by1)) w10 = 0.f;
    if (!(bx1 && by1)) w11 = 0.f;
    int xc0 = min(max(x0, 0), WW - 1);
    int xc1 = min(max(x0 + 1, 0), WW - 1);
    int yc0 = min(max(y0, 0), HH - 1);
    int yc1 = min(max(y0 + 1, 0), HH - 1);

    size_t fbase = (size_t)(b * CC + w) * HH * WW;
    const float4* f00 = (const float4*)(feat + (fbase + (size_t)yc0 * WW + xc0) * DD);
    const float4* f01 = (const float4*)(feat + (fbase + (size_t)yc0 * WW + xc1) * DD);
    const float4* f10 = (const float4*)(feat + (fbase + (size_t)yc1 * WW + xc0) * DD);
    const float4* f11 = (const float4*)(feat + (fbase + (size_t)yc1 * WW + xc1) * DD);
    const float4* t4 = (const float4*)(t + (size_t)bn * DD);

    float acc = 0.f;
    #pragma unroll
    for (int j = 0; j < 2; j++) {
        int q4 = lane + j * 32;
        float4 a0 = f00[q4], a1 = f01[q4], a2 = f10[q4], a3 = f11[q4];
        float4 s4;
        s4.x = w00 * a0.x + w01 * a1.x + w10 * a2.x + w11 * a3.x;
        s4.y = w00 * a0.y + w01 * a1.y + w10 * a2.y + w11 * a3.y;
        s4.z = w00 * a0.z + w01 * a1.z + w10 * a2.z + w11 * a3.z;
        s4.w = w00 * a0.w + w01 * a1.w + w10 * a2.w + w11 * a3.w;
        *(float4*)&samp[w][q4 * 4] = s4;
        float4 tv = t4[q4];
        acc += s4.x * tv.x + s4.y * tv.y + s4.z * tv.z + s4.w * tv.w;
    }
    #pragma unroll
    for (int o = 16; o > 0; o >>= 1) acc += __shfl_xor_sync(0xFFFFFFFFu, acc, o);
    if (lane == 0) {
        int vm = vmask[((size_t)b * CC + w) * NN + n];
        sc[w] = vm ? (acc + s_sb) * 0.0625f : -INFINITY;
    }
    __syncthreads();

    // softmax over C=8 (redundant per thread)
    float m = -INFINITY;
    #pragma unroll
    for (int c = 0; c < CC; c++) m = fmaxf(m, sc[c]);
    float a[CC];
    float ssum = 0.f;
    if (m == -INFINITY) {
        #pragma unroll
        for (int c = 0; c < CC; c++) a[c] = 0.f;
    } else {
        float denom = 0.f;
        #pragma unroll
        for (int c = 0; c < CC; c++) { a[c] = __expf(sc[c] - m); denom += a[c]; }
        float inv = 1.f / denom;
        #pragma unroll
        for (int c = 0; c < CC; c++) { a[c] *= inv; ssum += a[c]; }
    }

    float o = 0.f;
    #pragma unroll
    for (int c = 0; c < CC; c++) o += a[c] * samp[c][tid];
    u[(size_t)bn * DD + tid] = o;
    if (tid == 0) s_out[bn] = ssum;
}

// ---------------------------------------------------------------------------
// Launch
// ---------------------------------------------------------------------------
extern "C" void kernel_launch(void* const* d_in, const int* in_sizes, int n_in,
                              void* d_out, int out_size) {
    const float* queries = (const float*)d_in[0];
    const float* feat    = (const float*)d_in[1];
    const float* coords  = (const float*)d_in[2];
    const int*   vmask   = (const int*)d_in[3];
    const float* Wq      = (const float*)d_in[4];
    const float* bq      = (const float*)d_in[5];
    const float* Wkv     = (const float*)d_in[6];
    const float* bkv     = (const float*)d_in[7];
    const float* Wo      = (const float*)d_in[8];
    const float* bo      = (const float*)d_in[9];
    const float* gamma   = (const float*)d_in[10];
    const float* beta    = (const float*)d_in[11];
    float* out = (float*)d_out;

    float *p_qn, *p_t, *p_u, *p_s, *p_Wqk, *p_Wvo, *p_bqk, *p_bvo, *p_wqbk, *p_bqbk;
    cudaGetSymbolAddress((void**)&p_qn, g_qn);
    cudaGetSymbolAddress((void**)&p_t, g_t);
    cudaGetSymbolAddress((void**)&p_u, g_u);
    cudaGetSymbolAddress((void**)&p_s, g_s);
    cudaGetSymbolAddress((void**)&p_Wqk, g_Wqk);
    cudaGetSymbolAddress((void**)&p_Wvo, g_Wvo);
    cudaGetSymbolAddress((void**)&p_bqk, g_bqk);
    cudaGetSymbolAddress((void**)&p_bvo, g_bvo);
    cudaGetSymbolAddress((void**)&p_wqbk, g_wqbk);
    cudaGetSymbolAddress((void**)&p_bqbk, g_bqbk);

    const int Mq = BB * NN;   // 32768

    fold_kernel<<<514, 256>>>(Wq, bq, Wkv, bkv, Wo);
    ln_kernel<<<Mq, 256>>>(queries, gamma, beta, p_qn);
    // t = qn @ Wqk + bqk
    gemm_tf32_kernel<<<dim3(DD / 128, Mq / 128), 256>>>(
        p_qn, p_Wqk, p_bqk, nullptr, nullptr, nullptr, p_t, Mq, DD, DD);
    // fused sample + attention -> u, s
    fused_attn_kernel<<<Mq, 256>>>(feat, coords, vmask, p_qn, p_t,
                                   p_wqbk, p_bqbk, p_u, p_s);
    // out = queries + u @ Wvo + s*bvo + bo
    gemm_tf32_kernel<<<dim3(DD / 128, Mq / 128), 256>>>(
        p_u, p_Wvo, bo, queries, p_s, p_bvo, out, Mq, DD, DD);
}

// round 4
// speedup vs baseline: 7.4379x; 1.1093x over previous
#include <cuda_runtime.h>
#include <math.h>

// Problem constants
#define BB 2
#define NN 16384
#define CC 8
#define DD 256
#define HH 64
#define WW 64

// Scratch (device globals: allocation-free)
__device__ float g_t[(size_t)BB * NN * DD];      // 33.5 MB  (t = q @ Wk^T, pre-scaled by 1/16)
__device__ float g_u[(size_t)BB * NN * DD];      // 33.5 MB  (u = sum_c attn*sampled)
__device__ float g_s[(size_t)BB * NN];           // sum of attn per row
__device__ float g_Wqk[DD * DD];                 // Wq @ Wkv[:,:D]^T
__device__ float g_Wvo[DD * DD];                 // Wkv[:,D:] @ Wo
__device__ float g_bqk[DD];                      // bqk[j] = sum_d Wkv[j,d]*bq[d]
__device__ float g_bvo[DD];                      // bv @ Wo

__device__ __forceinline__ unsigned f2tf32(float f) {
    unsigned u;
    asm("cvt.rna.tf32.f32 %0, %1;" : "=r"(u) : "f"(f));
    return u;
}

// ---------------------------------------------------------------------------
// Weight folding (fp32, exact). 513 blocks x 256 threads.
// ---------------------------------------------------------------------------
__global__ void fold_kernel(const float* __restrict__ Wq,
                            const float* __restrict__ bq,
                            const float* __restrict__ Wkv,
                            const float* __restrict__ bkv,
                            const float* __restrict__ Wo) {
    __shared__ float srow[DD];
    int bidx = blockIdx.x;
    int tid = threadIdx.x;

    if (bidx < 256) {
        // Wqk[a][j] = sum_d Wq[a][d] * Wkv[j][d]
        srow[tid] = Wq[(size_t)bidx * DD + tid];
        __syncthreads();
        float acc = 0.f;
        const float* wr = Wkv + (size_t)tid * (2 * DD);
        #pragma unroll 4
        for (int d = 0; d < DD; d++) acc += srow[d] * wr[d];
        g_Wqk[(size_t)bidx * DD + tid] = acc;
    } else if (bidx < 512) {
        // Wvo[i][j] = sum_k Wkv[i][256+k] * Wo[k][j]
        int i = bidx - 256;
        srow[tid] = Wkv[(size_t)i * (2 * DD) + DD + tid];
        __syncthreads();
        float acc = 0.f;
        #pragma unroll 4
        for (int k = 0; k < DD; k++) acc += srow[k] * Wo[(size_t)k * DD + tid];
        g_Wvo[(size_t)i * DD + tid] = acc;
    } else {
        // bqk[j] = sum_d Wkv[j][d] * bq[d] ;  bvo[j] = sum_k bv[k] * Wo[k][j]
        float a1 = 0.f, a2 = 0.f;
        const float* wr = Wkv + (size_t)tid * (2 * DD);
        #pragma unroll 4
        for (int d = 0; d < DD; d++) a1 += wr[d] * bq[d];
        #pragma unroll 4
        for (int k = 0; k < DD; k++) a2 += bkv[DD + k] * Wo[(size_t)k * DD + tid];
        g_bqk[tid] = a1;
        g_bvo[tid] = a2;
    }
}

// ---------------------------------------------------------------------------
// TF32 tensor-core GEMM, BM=64 BN=128 BK=16, 256 threads (8 warps, 32x32 warp
// tiles), double-buffered, occupancy 2. Optional fused row-LayerNorm on A
// (DO_LN): each A-loader thread owns one row (row = tid>>2) and computes its
// mean/var in a quad-shuffle pre-pass, applying LN during tf32 conversion.
// Epilogue: C = scale*(A@W + bias [+ svec[r]*bvec2[c]]) [+ resid].
// Requires M%64==0, Nc%128==0, K==256 when DO_LN (gamma/beta staged by tid).
// ---------------------------------------------------------------------------
template <bool DO_LN>
__global__ void __launch_bounds__(256, 2)
gemm2_kernel(const float* __restrict__ A, const float* __restrict__ W,
             const float* __restrict__ bias, const float* __restrict__ resid,
             const float* __restrict__ svec, const float* __restrict__ bvec2,
             const float* __restrict__ gamma, const float* __restrict__ beta,
             float scale, float* __restrict__ Cm, int M, int K, int Nc) {
    const int BK = 16, LA = 72, LB = 136;
    __shared__ unsigned As[2][BK][LA];
    __shared__ unsigned Bs[2][BK][LB];
    __shared__ float sg[DD], sb[DD];

    int tid = threadIdx.x;
    int lane = tid & 31;
    int wid = tid >> 5;
    int wm = wid >> 2;          // 0..1
    int wn = wid & 3;           // 0..3
    int g = lane >> 2;          // 0..7
    int tg = lane & 3;          // 0..3

    size_t row0 = (size_t)blockIdx.y * 64;
    size_t col0 = (size_t)blockIdx.x * 128;

    int a_m = tid >> 2;         // 0..63 (row within tile; = LN row owner)
    int a_kq = tid & 3;         // float4 slot within 16-col k-tile
    int b_kk = tid >> 5;        // 0..7 (and +8)
    int b_nq = tid & 31;

    const float* Aptr = A + (row0 + a_m) * (size_t)K + a_kq * 4;
    const float* Bptr = W + (size_t)b_kk * Nc + col0 + b_nq * 4;

    float mu = 0.f, rs = 0.f;
    if (DO_LN) {
        sg[tid] = gamma[tid];
        sb[tid] = beta[tid];
        // quad pre-pass: 4 threads per row, each reads 64 consecutive floats
        const float4* rp = (const float4*)(A + (row0 + a_m) * (size_t)K + a_kq * 64);
        float s = 0.f, s2 = 0.f;
        #pragma unroll
        for (int i = 0; i < 16; i++) {
            float4 v = rp[i];
            s += v.x + v.y + v.z + v.w;
            s2 += v.x * v.x + v.y * v.y + v.z * v.z + v.w * v.w;
        }
        s += __shfl_xor_sync(0xFFFFFFFFu, s, 1);
        s += __shfl_xor_sync(0xFFFFFFFFu, s, 2);
        s2 += __shfl_xor_sync(0xFFFFFFFFu, s2, 1);
        s2 += __shfl_xor_sync(0xFFFFFFFFu, s2, 2);
        mu = s * (1.f / (float)DD);
        rs = rsqrtf(s2 * (1.f / (float)DD) - mu * mu + 1e-5f);
        __syncthreads();   // sg/sb visible to all
    }

    float acc[2][4][4];
    #pragma unroll
    for (int i = 0; i < 2; i++)
        #pragma unroll
        for (int j = 0; j < 4; j++)
            #pragma unroll
            for (int r = 0; r < 4; r++) acc[i][j][r] = 0.f;

    // prologue: k-tile 0 into buffer 0
    {
        float4 av = *(const float4*)(Aptr);
        float4 bv0 = *(const float4*)(Bptr);
        float4 bv1 = *(const float4*)(Bptr + 8 * (size_t)Nc);
        int kc = a_kq * 4;
        if (DO_LN) {
            As[0][kc + 0][a_m] = f2tf32((av.x - mu) * rs * sg[kc + 0] + sb[kc + 0]);
            As[0][kc + 1][a_m] = f2tf32((av.y - mu) * rs * sg[kc + 1] + sb[kc + 1]);
            As[0][kc + 2][a_m] = f2tf32((av.z - mu) * rs * sg[kc + 2] + sb[kc + 2]);
            As[0][kc + 3][a_m] = f2tf32((av.w - mu) * rs * sg[kc + 3] + sb[kc + 3]);
        } else {
            As[0][kc + 0][a_m] = f2tf32(av.x);
            As[0][kc + 1][a_m] = f2tf32(av.y);
            As[0][kc + 2][a_m] = f2tf32(av.z);
            As[0][kc + 3][a_m] = f2tf32(av.w);
        }
        Bs[0][b_kk][b_nq * 4 + 0] = f2tf32(bv0.x);
        Bs[0][b_kk][b_nq * 4 + 1] = f2tf32(bv0.y);
        Bs[0][b_kk][b_nq * 4 + 2] = f2tf32(bv0.z);
        Bs[0][b_kk][b_nq * 4 + 3] = f2tf32(bv0.w);
        Bs[0][b_kk + 8][b_nq * 4 + 0] = f2tf32(bv1.x);
        Bs[0][b_kk + 8][b_nq * 4 + 1] = f2tf32(bv1.y);
        Bs[0][b_kk + 8][b_nq * 4 + 2] = f2tf32(bv1.z);
        Bs[0][b_kk + 8][b_nq * 4 + 3] = f2tf32(bv1.w);
    }
    __syncthreads();

    int cur = 0;
    for (int k0 = 0; k0 < K; k0 += BK) {
        int nxt = k0 + BK;
        float4 av, bv0, bv1;
        if (nxt < K) {
            av = *(const float4*)(Aptr + nxt);
            bv0 = *(const float4*)(Bptr + (size_t)nxt * Nc);
            bv1 = *(const float4*)(Bptr + (size_t)(nxt + 8) * Nc);
        }

        #pragma unroll
        for (int ks = 0; ks < 2; ks++) {
            int kb = ks * 8;
            unsigned a[2][4], b[4][2];
            #pragma unroll
            for (int mt = 0; mt < 2; mt++) {
                int m = wm * 32 + mt * 16 + g;
                a[mt][0] = As[cur][kb + tg][m];
                a[mt][1] = As[cur][kb + tg][m + 8];
                a[mt][2] = As[cur][kb + tg + 4][m];
                a[mt][3] = As[cur][kb + tg + 4][m + 8];
            }
            #pragma unroll
            for (int nt = 0; nt < 4; nt++) {
                int n = wn * 32 + nt * 8 + g;
                b[nt][0] = Bs[cur][kb + tg][n];
                b[nt][1] = Bs[cur][kb + tg + 4][n];
            }
            #pragma unroll
            for (int mt = 0; mt < 2; mt++)
                #pragma unroll
                for (int nt = 0; nt < 4; nt++) {
                    asm volatile(
                        "mma.sync.aligned.m16n8k8.row.col.f32.tf32.tf32.f32 "
                        "{%0,%1,%2,%3}, {%4,%5,%6,%7}, {%8,%9}, {%0,%1,%2,%3};\n"
                        : "+f"(acc[mt][nt][0]), "+f"(acc[mt][nt][1]),
                          "+f"(acc[mt][nt][2]), "+f"(acc[mt][nt][3])
                        : "r"(a[mt][0]), "r"(a[mt][1]), "r"(a[mt][2]), "r"(a[mt][3]),
                          "r"(b[nt][0]), "r"(b[nt][1]));
                }
        }

        if (nxt < K) {
            int nx = cur ^ 1;
            int kc = a_kq * 4;
            if (DO_LN) {
                As[nx][kc + 0][a_m] = f2tf32((av.x - mu) * rs * sg[nxt + kc + 0] + sb[nxt + kc + 0]);
                As[nx][kc + 1][a_m] = f2tf32((av.y - mu) * rs * sg[nxt + kc + 1] + sb[nxt + kc + 1]);
                As[nx][kc + 2][a_m] = f2tf32((av.z - mu) * rs * sg[nxt + kc + 2] + sb[nxt + kc + 2]);
                As[nx][kc + 3][a_m] = f2tf32((av.w - mu) * rs * sg[nxt + kc + 3] + sb[nxt + kc + 3]);
            } else {
                As[nx][kc + 0][a_m] = f2tf32(av.x);
                As[nx][kc + 1][a_m] = f2tf32(av.y);
                As[nx][kc + 2][a_m] = f2tf32(av.z);
                As[nx][kc + 3][a_m] = f2tf32(av.w);
            }
            Bs[nx][b_kk][b_nq * 4 + 0] = f2tf32(bv0.x);
            Bs[nx][b_kk][b_nq * 4 + 1] = f2tf32(bv0.y);
            Bs[nx][b_kk][b_nq * 4 + 2] = f2tf32(bv0.z);
            Bs[nx][b_kk][b_nq * 4 + 3] = f2tf32(bv0.w);
            Bs[nx][b_kk + 8][b_nq * 4 + 0] = f2tf32(bv1.x);
            Bs[nx][b_kk + 8][b_nq * 4 + 1] = f2tf32(bv1.y);
            Bs[nx][b_kk + 8][b_nq * 4 + 2] = f2tf32(bv1.z);
            Bs[nx][b_kk + 8][b_nq * 4 + 3] = f2tf32(bv1.w);
            __syncthreads();
        }
        cur ^= 1;
    }

    #pragma unroll
    for (int mt = 0; mt < 2; mt++) {
        size_t r = row0 + wm * 32 + mt * 16 + g;
        #pragma unroll
        for (int nt = 0; nt < 4; nt++) {
            size_t c = col0 + wn * 32 + nt * 8 + tg * 2;
            float2 bb = *(const float2*)(bias + c);
            float2 v0, v1;
            v0.x = acc[mt][nt][0] + bb.x;
            v0.y = acc[mt][nt][1] + bb.y;
            v1.x = acc[mt][nt][2] + bb.x;
            v1.y = acc[mt][nt][3] + bb.y;
            if (svec) {
                float2 b2 = *(const float2*)(bvec2 + c);
                float s0 = svec[r], s1 = svec[r + 8];
                v0.x += s0 * b2.x; v0.y += s0 * b2.y;
                v1.x += s1 * b2.x; v1.y += s1 * b2.y;
            }
            v0.x *= scale; v0.y *= scale; v1.x *= scale; v1.y *= scale;
            if (resid) {
                float2 r0 = *(const float2*)(resid + r * Nc + c);
                float2 r1 = *(const float2*)(resid + (r + 8) * Nc + c);
                v0.x += r0.x; v0.y += r0.y;
                v1.x += r1.x; v1.y += r1.y;
            }
            *(float2*)(Cm + r * Nc + c) = v0;
            *(float2*)(Cm + (r + 8) * Nc + c) = v1;
        }
    }
}

// ---------------------------------------------------------------------------
// Fused bilinear-sample + score + softmax + weighted-sum.
// One block per (b,n), 256 threads; warp c handles channel c.
//   score[c] = sampled[n,c] . t[n]      (t pre-scaled by 1/sqrt(D); the q.bk
//              shift is constant over c and cancels in softmax)
//   u[n]     = sum_c softmax(score)[c] * sampled[n,c]
//   s[n]     = sum_c softmax(score)[c]   (0 if all channels masked)
// ---------------------------------------------------------------------------
__global__ void fused_attn_kernel(const float* __restrict__ feat,
                                  const float* __restrict__ coords,
                                  const int* __restrict__ vmask,
                                  const float* __restrict__ t,
                                  float* __restrict__ u,
                                  float* __restrict__ s_out) {
    int bn = blockIdx.x;
    int b = bn >> 14;           // NN = 16384
    int n = bn & (NN - 1);
    int tid = threadIdx.x;
    int w = tid >> 5, lane = tid & 31;

    __shared__ float samp[CC][DD];
    __shared__ float sc[CC];

    // bilinear sample for channel w + dot with t[n]
    const float* pc = coords + ((size_t)(b * CC + w) * NN + n) * 2;
    float xf = (pc[0] + 1.f) * 0.5f * (float)(WW - 1);
    float yf = (pc[1] + 1.f) * 0.5f * (float)(HH - 1);
    float x0f = floorf(xf), y0f = floorf(yf);
    float wx = xf - x0f, wy = yf - y0f;
    int x0 = (int)x0f, y0 = (int)y0f;
    float w00 = (1.f - wy) * (1.f - wx);
    float w01 = (1.f - wy) * wx;
    float w10 = wy * (1.f - wx);
    float w11 = wy * wx;
    bool bx0 = (x0 >= 0) && (x0 < WW);
    bool bx1 = (x0 + 1 >= 0) && (x0 + 1 < WW);
    bool by0 = (y0 >= 0) && (y0 < HH);
    bool by1 = (y0 + 1 >= 0) && (y0 + 1 < HH);
    if (!(bx0 && by0)) w00 = 0.f;
    if (!(bx1 && by0)) w01 = 0.f;
    if (!(bx0 && by1)) w10 = 0.f;
    if (!(bx1 && by1)) w11 = 0.f;
    int xc0 = min(max(x0, 0), WW - 1);
    int xc1 = min(max(x0 + 1, 0), WW - 1);
    int yc0 = min(max(y0, 0), HH - 1);
    int yc1 = min(max(y0 + 1, 0), HH - 1);

    size_t fbase = (size_t)(b * CC + w) * HH * WW;
    const float4* f00 = (const float4*)(feat + (fbase + (size_t)yc0 * WW + xc0) * DD);
    const float4* f01 = (const float4*)(feat + (fbase + (size_t)yc0 * WW + xc1) * DD);
    const float4* f10 = (const float4*)(feat + (fbase + (size_t)yc1 * WW + xc0) * DD);
    const float4* f11 = (const float4*)(feat + (fbase + (size_t)yc1 * WW + xc1) * DD);
    const float4* t4 = (const float4*)(t + (size_t)bn * DD);

    float acc = 0.f;
    #pragma unroll
    for (int j = 0; j < 2; j++) {
        int q4 = lane + j * 32;
        float4 a0 = f00[q4], a1 = f01[q4], a2 = f10[q4], a3 = f11[q4];
        float4 s4;
        s4.x = w00 * a0.x + w01 * a1.x + w10 * a2.x + w11 * a3.x;
        s4.y = w00 * a0.y + w01 * a1.y + w10 * a2.y + w11 * a3.y;
        s4.z = w00 * a0.z + w01 * a1.z + w10 * a2.z + w11 * a3.z;
        s4.w = w00 * a0.w + w01 * a1.w + w10 * a2.w + w11 * a3.w;
        *(float4*)&samp[w][q4 * 4] = s4;
        float4 tv = t4[q4];
        acc += s4.x * tv.x + s4.y * tv.y + s4.z * tv.z + s4.w * tv.w;
    }
    #pragma unroll
    for (int o = 16; o > 0; o >>= 1) acc += __shfl_xor_sync(0xFFFFFFFFu, acc, o);
    if (lane == 0) {
        int vm = vmask[((size_t)b * CC + w) * NN + n];
        sc[w] = vm ? acc : -INFINITY;
    }
    __syncthreads();

    // softmax over C=8 (redundant per thread)
    float m = -INFINITY;
    #pragma unroll
    for (int c = 0; c < CC; c++) m = fmaxf(m, sc[c]);
    float a[CC];
    float ssum = 0.f;
    if (m == -INFINITY) {
        #pragma unroll
        for (int c = 0; c < CC; c++) a[c] = 0.f;
    } else {
        float denom = 0.f;
        #pragma unroll
        for (int c = 0; c < CC; c++) { a[c] = __expf(sc[c] - m); denom += a[c]; }
        float inv = 1.f / denom;
        #pragma unroll
        for (int c = 0; c < CC; c++) { a[c] *= inv; ssum += a[c]; }
    }

    float o = 0.f;
    #pragma unroll
    for (int c = 0; c < CC; c++) o += a[c] * samp[c][tid];
    u[(size_t)bn * DD + tid] = o;
    if (tid == 0) s_out[bn] = ssum;
}

// ---------------------------------------------------------------------------
// Launch
// ---------------------------------------------------------------------------
extern "C" void kernel_launch(void* const* d_in, const int* in_sizes, int n_in,
                              void* d_out, int out_size) {
    const float* queries = (const float*)d_in[0];
    const float* feat    = (const float*)d_in[1];
    const float* coords  = (const float*)d_in[2];
    const int*   vmask   = (const int*)d_in[3];
    const float* Wq      = (const float*)d_in[4];
    const float* bq      = (const float*)d_in[5];
    const float* Wkv     = (const float*)d_in[6];
    const float* bkv     = (const float*)d_in[7];
    const float* Wo      = (const float*)d_in[8];
    const float* bo      = (const float*)d_in[9];
    const float* gamma   = (const float*)d_in[10];
    const float* beta    = (const float*)d_in[11];
    float* out = (float*)d_out;

    float *p_t, *p_u, *p_s, *p_Wqk, *p_Wvo, *p_bqk, *p_bvo;
    cudaGetSymbolAddress((void**)&p_t, g_t);
    cudaGetSymbolAddress((void**)&p_u, g_u);
    cudaGetSymbolAddress((void**)&p_s, g_s);
    cudaGetSymbolAddress((void**)&p_Wqk, g_Wqk);
    cudaGetSymbolAddress((void**)&p_Wvo, g_Wvo);
    cudaGetSymbolAddress((void**)&p_bqk, g_bqk);
    cudaGetSymbolAddress((void**)&p_bvo, g_bvo);

    const int Mq = BB * NN;   // 32768

    fold_kernel<<<513, 256>>>(Wq, bq, Wkv, bkv, Wo);
    // t = LN(queries) @ Wqk + bqk, scaled by 1/sqrt(D)=1/16, LN fused into A-load
    gemm2_kernel<true><<<dim3(DD / 128, Mq / 64), 256>>>(
        queries, p_Wqk, p_bqk, nullptr, nullptr, nullptr,
        gamma, beta, 0.0625f, p_t, Mq, DD, DD);
    // fused sample + attention -> u, s
    fused_attn_kernel<<<Mq, 256>>>(feat, coords, vmask, p_t, p_u, p_s);
    // out = queries + u @ Wvo + s*bvo + bo
    gemm2_kernel<false><<<dim3(DD / 128, Mq / 64), 256>>>(
        p_u, p_Wvo, bo, queries, p_s, p_bvo,
        nullptr, nullptr, 1.0f, out, Mq, DD, DD);
}

// round 5
// speedup vs baseline: 7.6222x; 1.0248x over previous
#include <cuda_runtime.h>
#include <math.h>

// Problem constants
#define BB 2
#define NN 16384
#define CC 8
#define DD 256
#define HH 64
#define WW 64

// Scratch (device globals: allocation-free)
__device__ float g_t[(size_t)BB * NN * DD];      // t = LN(q) @ Wqk + bqk, scaled 1/16
__device__ float g_u[(size_t)BB * NN * DD];      // u = sum_c attn*sampled
__device__ float g_s[(size_t)BB * NN];           // sum of attn per row (0 or 1)
__device__ float g_Wqk[DD * DD];                 // Wq @ Wkv[:,:D]^T
__device__ float g_Wvo[DD * DD];                 // Wkv[:,D:] @ Wo
__device__ float g_bqk[DD];                      // bqk[j] = sum_d Wkv[j,d]*bq[d]
__device__ float g_bvo[DD];                      // bv @ Wo

__device__ __forceinline__ void cp16(void* smem_dst, const void* gmem_src) {
    unsigned s = (unsigned)__cvta_generic_to_shared(smem_dst);
    asm volatile("cp.async.cg.shared.global [%0], [%1], 16;" :: "r"(s), "l"(gmem_src));
}
#define CP_COMMIT() asm volatile("cp.async.commit_group;")
#define CP_WAIT0()  asm volatile("cp.async.wait_group 0;")

// ---------------------------------------------------------------------------
// Weight folding (fp32, exact). 513 blocks x 256 threads.
// ---------------------------------------------------------------------------
__global__ void fold_kernel(const float* __restrict__ Wq,
                            const float* __restrict__ bq,
                            const float* __restrict__ Wkv,
                            const float* __restrict__ bkv,
                            const float* __restrict__ Wo) {
    __shared__ float srow[DD];
    int bidx = blockIdx.x;
    int tid = threadIdx.x;

    if (bidx < 256) {
        srow[tid] = Wq[(size_t)bidx * DD + tid];
        __syncthreads();
        float acc = 0.f;
        const float* wr = Wkv + (size_t)tid * (2 * DD);
        #pragma unroll 4
        for (int d = 0; d < DD; d++) acc += srow[d] * wr[d];
        g_Wqk[(size_t)bidx * DD + tid] = acc;
    } else if (bidx < 512) {
        int i = bidx - 256;
        srow[tid] = Wkv[(size_t)i * (2 * DD) + DD + tid];
        __syncthreads();
        float acc = 0.f;
        #pragma unroll 4
        for (int k = 0; k < DD; k++) acc += srow[k] * Wo[(size_t)k * DD + tid];
        g_Wvo[(size_t)i * DD + tid] = acc;
    } else {
        float a1 = 0.f, a2 = 0.f;
        const float* wr = Wkv + (size_t)tid * (2 * DD);
        #pragma unroll 4
        for (int d = 0; d < DD; d++) a1 += wr[d] * bq[d];
        #pragma unroll 4
        for (int k = 0; k < DD; k++) a2 += bkv[DD + k] * Wo[(size_t)k * DD + tid];
        g_bqk[tid] = a1;
        g_bvo[tid] = a2;
    }
}

// ---------------------------------------------------------------------------
// TF32 tensor-core GEMM, BM=64 BN=128 BK=16, 256 threads (8 warps, 32x32 warp
// tiles), cp.async double-buffered pipeline, raw fp32 fed to tf32 MMA (HW
// truncates mantissa - no cvt instructions). A stored [m][k] with LDA=20
// (16B-aligned rows, conflict-free fragment banks). Optional fused row-LN on A.
// Epilogue: C = scale*(A@W + bias [+ svec[r]*bvec2[c]]) [+ resid].
// ---------------------------------------------------------------------------
template <bool DO_LN>
__global__ void __launch_bounds__(256, 2)
gemm2_kernel(const float* __restrict__ A, const float* __restrict__ W,
             const float* __restrict__ bias, const float* __restrict__ resid,
             const float* __restrict__ svec, const float* __restrict__ bvec2,
             const float* __restrict__ gamma, const float* __restrict__ beta,
             float scale, float* __restrict__ Cm, int M, int K, int Nc) {
    const int BK = 16, LDA = 20, LDB = 136;
    __shared__ unsigned As[2][64][LDA];   // [buf][m][k], row = 80B (16B-aligned)
    __shared__ unsigned Bs[2][BK][LDB];   // [buf][k][n]
    __shared__ float sg[DD], sb[DD];

    int tid = threadIdx.x;
    int lane = tid & 31;
    int wid = tid >> 5;
    int wm = wid >> 2;          // 0..1
    int wn = wid & 3;           // 0..3
    int g = lane >> 2;          // 0..7
    int tg = lane & 3;          // 0..3

    size_t row0 = (size_t)blockIdx.y * 64;
    size_t col0 = (size_t)blockIdx.x * 128;

    int a_m = tid >> 2;         // 0..63 (row; LN owner)
    int a_kq = tid & 3;         // 16B slot within 16-col k-tile
    int b_kk = tid >> 5;        // 0..7 (and +8)
    int b_nq = tid & 31;

    const float* Aptr = A + (row0 + a_m) * (size_t)K + a_kq * 4;
    const float* Bptr = W + (size_t)b_kk * Nc + col0 + b_nq * 4;

    float mu = 0.f, rs = 0.f;
    if (DO_LN) {
        sg[tid] = gamma[tid];
        sb[tid] = beta[tid];
        // quad pre-pass: 4 threads per row, each reads 64 consecutive floats
        const float4* rp = (const float4*)(A + (row0 + a_m) * (size_t)K + a_kq * 64);
        float s = 0.f, s2 = 0.f;
        #pragma unroll
        for (int i = 0; i < 16; i++) {
            float4 v = rp[i];
            s += v.x + v.y + v.z + v.w;
            s2 += v.x * v.x + v.y * v.y + v.z * v.z + v.w * v.w;
        }
        s += __shfl_xor_sync(0xFFFFFFFFu, s, 1);
        s += __shfl_xor_sync(0xFFFFFFFFu, s, 2);
        s2 += __shfl_xor_sync(0xFFFFFFFFu, s2, 1);
        s2 += __shfl_xor_sync(0xFFFFFFFFu, s2, 2);
        mu = s * (1.f / (float)DD);
        rs = rsqrtf(s2 * (1.f / (float)DD) - mu * mu + 1e-5f);
        __syncthreads();   // sg/sb visible
    }

    float acc[2][4][4];
    #pragma unroll
    for (int i = 0; i < 2; i++)
        #pragma unroll
        for (int j = 0; j < 4; j++)
            #pragma unroll
            for (int r = 0; r < 4; r++) acc[i][j][r] = 0.f;

    const int NT = K / BK;   // 16

    // ---- prologue: tile 0 into buffer 0
    if (DO_LN) {
        float4 av = *(const float4*)(Aptr);
        int kc = a_kq * 4;
        As[0][a_m][kc + 0] = __float_as_uint((av.x - mu) * rs * sg[kc + 0] + sb[kc + 0]);
        As[0][a_m][kc + 1] = __float_as_uint((av.y - mu) * rs * sg[kc + 1] + sb[kc + 1]);
        As[0][a_m][kc + 2] = __float_as_uint((av.z - mu) * rs * sg[kc + 2] + sb[kc + 2]);
        As[0][a_m][kc + 3] = __float_as_uint((av.w - mu) * rs * sg[kc + 3] + sb[kc + 3]);
    } else {
        cp16(&As[0][a_m][a_kq * 4], Aptr);
    }
    cp16(&Bs[0][b_kk][b_nq * 4], Bptr);
    cp16(&Bs[0][b_kk + 8][b_nq * 4], Bptr + 8 * (size_t)Nc);
    CP_COMMIT();
    CP_WAIT0();
    __syncthreads();

    int cur = 0;
    for (int it = 0; it < NT; it++) {
        int nxt = it + 1;
        int nx = cur ^ 1;

        // start async loads for next tile (overlap with mma below)
        if (nxt < NT) {
            if (!DO_LN) cp16(&As[nx][a_m][a_kq * 4], Aptr + nxt * BK);
            cp16(&Bs[nx][b_kk][b_nq * 4], Bptr + (size_t)(nxt * BK) * Nc);
            cp16(&Bs[nx][b_kk + 8][b_nq * 4], Bptr + (size_t)(nxt * BK + 8) * Nc);
            CP_COMMIT();
        }
        float4 av;
        if (DO_LN && nxt < NT) av = *(const float4*)(Aptr + nxt * BK);

        // ---- mma on buffer cur
        #pragma unroll
        for (int ks = 0; ks < 2; ks++) {
            int kb = ks * 8;
            unsigned a[2][4], b[4][2];
            #pragma unroll
            for (int mt = 0; mt < 2; mt++) {
                int m = wm * 32 + mt * 16 + g;
                a[mt][0] = As[cur][m][kb + tg];
                a[mt][1] = As[cur][m + 8][kb + tg];
                a[mt][2] = As[cur][m][kb + tg + 4];
                a[mt][3] = As[cur][m + 8][kb + tg + 4];
            }
            #pragma unroll
            for (int nt = 0; nt < 4; nt++) {
                int n = wn * 32 + nt * 8 + g;
                b[nt][0] = Bs[cur][kb + tg][n];
                b[nt][1] = Bs[cur][kb + tg + 4][n];
            }
            #pragma unroll
            for (int mt = 0; mt < 2; mt++)
                #pragma unroll
                for (int nt = 0; nt < 4; nt++) {
                    asm volatile(
                        "mma.sync.aligned.m16n8k8.row.col.f32.tf32.tf32.f32 "
                        "{%0,%1,%2,%3}, {%4,%5,%6,%7}, {%8,%9}, {%0,%1,%2,%3};\n"
                        : "+f"(acc[mt][nt][0]), "+f"(acc[mt][nt][1]),
                          "+f"(acc[mt][nt][2]), "+f"(acc[mt][nt][3])
                        : "r"(a[mt][0]), "r"(a[mt][1]), "r"(a[mt][2]), "r"(a[mt][3]),
                          "r"(b[nt][0]), "r"(b[nt][1]));
                }
        }

        if (nxt < NT) {
            if (DO_LN) {
                int kc = a_kq * 4;
                int kg = nxt * BK + kc;
                As[nx][a_m][kc + 0] = __float_as_uint((av.x - mu) * rs * sg[kg + 0] + sb[kg + 0]);
                As[nx][a_m][kc + 1] = __float_as_uint((av.y - mu) * rs * sg[kg + 1] + sb[kg + 1]);
                As[nx][a_m][kc + 2] = __float_as_uint((av.z - mu) * rs * sg[kg + 2] + sb[kg + 2]);
                As[nx][a_m][kc + 3] = __float_as_uint((av.w - mu) * rs * sg[kg + 3] + sb[kg + 3]);
            }
            CP_WAIT0();
            __syncthreads();
        }
        cur ^= 1;
    }

    // ---- epilogue
    #pragma unroll
    for (int mt = 0; mt < 2; mt++) {
        size_t r = row0 + wm * 32 + mt * 16 + g;
        #pragma unroll
        for (int nt = 0; nt < 4; nt++) {
            size_t c = col0 + wn * 32 + nt * 8 + tg * 2;
            float2 bb = *(const float2*)(bias + c);
            float2 v0, v1;
            v0.x = acc[mt][nt][0] + bb.x;
            v0.y = acc[mt][nt][1] + bb.y;
            v1.x = acc[mt][nt][2] + bb.x;
            v1.y = acc[mt][nt][3] + bb.y;
            if (svec) {
                float2 b2 = *(const float2*)(bvec2 + c);
                float s0 = svec[r], s1 = svec[r + 8];
                v0.x += s0 * b2.x; v0.y += s0 * b2.y;
                v1.x += s1 * b2.x; v1.y += s1 * b2.y;
            }
            v0.x *= scale; v0.y *= scale; v1.x *= scale; v1.y *= scale;
            if (resid) {
                float2 r0 = *(const float2*)(resid + r * Nc + c);
                float2 r1 = *(const float2*)(resid + (r + 8) * Nc + c);
                v0.x += r0.x; v0.y += r0.y;
                v1.x += r1.x; v1.y += r1.y;
            }
            *(float2*)(Cm + r * Nc + c) = v0;
            *(float2*)(Cm + (r + 8) * Nc + c) = v1;
        }
    }
}

// ---------------------------------------------------------------------------
// Fused bilinear-sample + score + softmax + weighted-sum.
// One block per (b,n), 256 threads; warp c handles channel c. Masked channels
// (vmask==0 -> attn weight exactly 0) skip the gather/blend/dot entirely.
// ---------------------------------------------------------------------------
__global__ void fused_attn_kernel(const float* __restrict__ feat,
                                  const float* __restrict__ coords,
                                  const int* __restrict__ vmask,
                                  const float* __restrict__ t,
                                  float* __restrict__ u,
                                  float* __restrict__ s_out) {
    int bn = blockIdx.x;
    int b = bn >> 14;           // NN = 16384
    int n = bn & (NN - 1);
    int tid = threadIdx.x;
    int w = tid >> 5, lane = tid & 31;

    __shared__ float samp[CC][DD];
    __shared__ float sc[CC];

    int vm = vmask[((size_t)b * CC + w) * NN + n];

    if (vm) {
        // bilinear sample for channel w + dot with t[n]
        const float* pc = coords + ((size_t)(b * CC + w) * NN + n) * 2;
        float xf = (pc[0] + 1.f) * 0.5f * (float)(WW - 1);
        float yf = (pc[1] + 1.f) * 0.5f * (float)(HH - 1);
        float x0f = floorf(xf), y0f = floorf(yf);
        float wx = xf - x0f, wy = yf - y0f;
        int x0 = (int)x0f, y0 = (int)y0f;
        float w00 = (1.f - wy) * (1.f - wx);
        float w01 = (1.f - wy) * wx;
        float w10 = wy * (1.f - wx);
        float w11 = wy * wx;
        bool bx0 = (x0 >= 0) && (x0 < WW);
        bool bx1 = (x0 + 1 >= 0) && (x0 + 1 < WW);
        bool by0 = (y0 >= 0) && (y0 < HH);
        bool by1 = (y0 + 1 >= 0) && (y0 + 1 < HH);
        if (!(bx0 && by0)) w00 = 0.f;
        if (!(bx1 && by0)) w01 = 0.f;
        if (!(bx0 && by1)) w10 = 0.f;
        if (!(bx1 && by1)) w11 = 0.f;
        int xc0 = min(max(x0, 0), WW - 1);
        int xc1 = min(max(x0 + 1, 0), WW - 1);
        int yc0 = min(max(y0, 0), HH - 1);
        int yc1 = min(max(y0 + 1, 0), HH - 1);

        size_t fbase = (size_t)(b * CC + w) * HH * WW;
        const float4* f00 = (const float4*)(feat + (fbase + (size_t)yc0 * WW + xc0) * DD);
        const float4* f01 = (const float4*)(feat + (fbase + (size_t)yc0 * WW + xc1) * DD);
        const float4* f10 = (const float4*)(feat + (fbase + (size_t)yc1 * WW + xc0) * DD);
        const float4* f11 = (const float4*)(feat + (fbase + (size_t)yc1 * WW + xc1) * DD);
        const float4* t4 = (const float4*)(t + (size_t)bn * DD);

        float acc = 0.f;
        #pragma unroll
        for (int j = 0; j < 2; j++) {
            int q4 = lane + j * 32;
            float4 a0 = f00[q4], a1 = f01[q4], a2 = f10[q4], a3 = f11[q4];
            float4 s4;
            s4.x = w00 * a0.x + w01 * a1.x + w10 * a2.x + w11 * a3.x;
            s4.y = w00 * a0.y + w01 * a1.y + w10 * a2.y + w11 * a3.y;
            s4.z = w00 * a0.z + w01 * a1.z + w10 * a2.z + w11 * a3.z;
            s4.w = w00 * a0.w + w01 * a1.w + w10 * a2.w + w11 * a3.w;
            *(float4*)&samp[w][q4 * 4] = s4;
            float4 tv = t4[q4];
            acc += s4.x * tv.x + s4.y * tv.y + s4.z * tv.z + s4.w * tv.w;
        }
        #pragma unroll
        for (int o = 16; o > 0; o >>= 1) acc += __shfl_xor_sync(0xFFFFFFFFu, acc, o);
        if (lane == 0) sc[w] = acc;
    } else {
        if (lane == 0) sc[w] = -INFINITY;
    }
    __syncthreads();

    // softmax over C=8 (redundant per thread)
    float m = -INFINITY;
    #pragma unroll
    for (int c = 0; c < CC; c++) m = fmaxf(m, sc[c]);
    float o = 0.f;
    float ssum = 0.f;
    if (m != -INFINITY) {
        float a[CC];
        float denom = 0.f;
        #pragma unroll
        for (int c = 0; c < CC; c++) { a[c] = __expf(sc[c] - m); denom += a[c]; }
        float inv = 1.f / denom;
        ssum = 1.f;
        #pragma unroll
        for (int c = 0; c < CC; c++) {
            if (sc[c] != -INFINITY) o += (a[c] * inv) * samp[c][tid];
        }
    }
    u[(size_t)bn * DD + tid] = o;
    if (tid == 0) s_out[bn] = ssum;
}

// ---------------------------------------------------------------------------
// Launch
// ---------------------------------------------------------------------------
extern "C" void kernel_launch(void* const* d_in, const int* in_sizes, int n_in,
                              void* d_out, int out_size) {
    const float* queries = (const float*)d_in[0];
    const float* feat    = (const float*)d_in[1];
    const float* coords  = (const float*)d_in[2];
    const int*   vmask   = (const int*)d_in[3];
    const float* Wq      = (const float*)d_in[4];
    const float* bq      = (const float*)d_in[5];
    const float* Wkv     = (const float*)d_in[6];
    const float* bkv     = (const float*)d_in[7];
    const float* Wo      = (const float*)d_in[8];
    const float* bo      = (const float*)d_in[9];
    const float* gamma   = (const float*)d_in[10];
    const float* beta    = (const float*)d_in[11];
    float* out = (float*)d_out;

    float *p_t, *p_u, *p_s, *p_Wqk, *p_Wvo, *p_bqk, *p_bvo;
    cudaGetSymbolAddress((void**)&p_t, g_t);
    cudaGetSymbolAddress((void**)&p_u, g_u);
    cudaGetSymbolAddress((void**)&p_s, g_s);
    cudaGetSymbolAddress((void**)&p_Wqk, g_Wqk);
    cudaGetSymbolAddress((void**)&p_Wvo, g_Wvo);
    cudaGetSymbolAddress((void**)&p_bqk, g_bqk);
    cudaGetSymbolAddress((void**)&p_bvo, g_bvo);

    const int Mq = BB * NN;   // 32768

    fold_kernel<<<513, 256>>>(Wq, bq, Wkv, bkv, Wo);
    // t = LN(queries) @ Wqk + bqk, scaled by 1/16, LN fused into A-load
    gemm2_kernel<true><<<dim3(DD / 128, Mq / 64), 256>>>(
        queries, p_Wqk, p_bqk, nullptr, nullptr, nullptr,
        gamma, beta, 0.0625f, p_t, Mq, DD, DD);
    // fused sample + attention -> u, s
    fused_attn_kernel<<<Mq, 256>>>(feat, coords, vmask, p_t, p_u, p_s);
    // out = queries + u @ Wvo + s*bvo + bo
    gemm2_kernel<false><<<dim3(DD / 128, Mq / 64), 256>>>(
        p_u, p_Wvo, bo, queries, p_s, p_bvo,
        nullptr, nullptr, 1.0f, out, Mq, DD, DD);
}